// round 12
// baseline (speedup 1.0000x reference)
#include <cuda_runtime.h>

// Shapes fixed by setup_inputs
#define B_ 64
#define T_ 4096
#define F_ 64
#define H_ 256
#define EPSV 1e-8f

// Chunked scan: lambda=0.5 -> 32-step warm-up error ~0.5^32.
#define CHUNK 64
#define NCHUNK (T_ / CHUNK)        // 64
#define WARM 32

#define NROWS (B_ * T_)            // 262144 fg rows
#define NFGB (NROWS / 8)           // 32768 fg blocks (8 warps = 8 rows each)
#define NM 16                      // mse blocks appended to kernel 1
#define NSCB (B_ * NCHUNK / 4)     // 1024 scan blocks (4 chunks each, 256 thr)

__device__ float g_fgsum[NROWS];   // sum_h fg per (b,t)   (1 MB)
__device__ float g_mse[NM];
__device__ float g_part[NSCB];
__device__ unsigned int g_cnt = 0;

// ---------------------------------------------------------------------------
// Kernel 1: PURE fg reduction (proven to run at the LTS cap) + MSE blocks.
// One warp per 1KB row, 2x float4 per lane.
// ---------------------------------------------------------------------------
__global__ void __launch_bounds__(256) k_fgsum(const float4* __restrict__ fg,
                                               const float4* __restrict__ inp,
                                               const float4* __restrict__ tgt) {
    int tid = threadIdx.x;
    int lane = tid & 31;

    if (blockIdx.x < NFGB) {
        int row = blockIdx.x * 8 + (tid >> 5);
        const float4* rp = fg + (size_t)row * (H_ / 4);
        float4 a = rp[lane];
        float4 b = rp[lane + 32];
        float s = (a.x + a.y) + (a.z + a.w) + (b.x + b.y) + (b.z + b.w);
#pragma unroll
        for (int o = 16; o > 0; o >>= 1) s += __shfl_xor_sync(0xffffffffu, s, o);
        if (lane == 0) g_fgsum[row] = s;
    } else {
        // ---- MSE role ----
        int mi = blockIdx.x - NFGB;
        const int n4 = (B_ * T_) / 4;
        float acc = 0.f;
        for (int i = mi * 256 + tid; i < n4; i += NM * 256) {
            float4 a = inp[i], b = tgt[i];
            float dx = a.x - b.x, dy = a.y - b.y, dz = a.z - b.z, dw = a.w - b.w;
            acc += dx * dx + dy * dy + dz * dz + dw * dw;
        }
#pragma unroll
        for (int o = 16; o > 0; o >>= 1) acc += __shfl_xor_sync(0xffffffffu, acc, o);
        __shared__ float sh[8];
        if (lane == 0) sh[tid >> 5] = acc;
        __syncthreads();
        if (tid == 0) {
            float s = 0.f;
            for (int w = 0; w < 8; ++w) s += sh[w];
            g_mse[mi] = s * (1.0f / ((float)B_ * T_));
        }
    }
}

// ---------------------------------------------------------------------------
// Kernel 2: PURE scan, high-occupancy. Block = 256 thr = 4 chunks; thread
// f-lane = tid&63. Private acc, fgsum via __ldg broadcast (L1/L2-hot, 1MB).
// Last arriving block folds g_part + g_mse into the output scalar.
// ---------------------------------------------------------------------------
__global__ void __launch_bounds__(256) k_scan(const float* __restrict__ seq,
                                              float* __restrict__ out) {
    int tid = threadIdx.x;
    int warp = tid >> 5, lane = tid & 31;

    int ci = blockIdx.x * 4 + (tid >> 6);   // global chunk index 0..4095
    int b = ci >> 6;                        // NCHUNK = 64
    int chunk = ci & 63;
    int t0 = chunk * CHUNK;

    const float* base = seq + (size_t)b * T_ * F_ + (tid & 63);
    const float* fgs = g_fgsum + b * T_;

    int first = (chunk == 0);
    int ts = first ? 1 : (t0 - WARM);

    float m = 0.f, v = EPSV, c = 0.f;
    float xl = __ldg(base + (size_t)(ts - 1) * F_);
    float acc = first ? __ldg(fgs) : 0.f;       // t=0 pad: irr==1

    // warm-up, no accumulation (chunk > 0 only)
#pragma unroll 8
    for (int t = ts; t < t0; ++t) {
        float xt = __ldg(base + (size_t)t * F_);
        m = 0.5f * (m + xt);
        float d = xt - m;
        v = 0.5f * (v + d * d);
        c = 0.5f * (c + d * (xl - m));
        xl = xt;
    }

    int tb = first ? 1 : t0;
#pragma unroll 8
    for (int t = tb; t < t0 + CHUNK; ++t) {
        float xt = __ldg(base + (size_t)t * F_);
        m = 0.5f * (m + xt);
        float d = xt - m;
        v = 0.5f * (v + d * d);
        c = 0.5f * (c + d * (xl - m));
        xl = xt;
        float ac = c * rsqrtf(v * v + EPSV);
        acc += (1.0f - fabsf(ac)) * __ldg(fgs + t);
    }

    // block-wide reduce (all 4 chunks share the same scale)
#pragma unroll
    for (int o = 16; o > 0; o >>= 1) acc += __shfl_xor_sync(0xffffffffu, acc, o);
    __shared__ float sh[8];
    __shared__ int is_last;
    if (lane == 0) sh[warp] = acc;
    __syncthreads();
    if (tid == 0) {
        float s = 0.f;
        for (int w = 0; w < 8; ++w) s += sh[w];
        // ALPHA / (B*T*H*F) = 0.5 / 2^32
        g_part[blockIdx.x] = s * (0.5f / 4294967296.0f);
        __threadfence();
        unsigned int t = atomicAdd(&g_cnt, 1u);
        is_last = (t == NSCB - 1);
    }
    __syncthreads();
    if (is_last) {
        double s = 0.0;
        for (int i = tid; i < NSCB; i += 256) s += (double)g_part[i];
        if (tid < NM) s += (double)g_mse[tid];
#pragma unroll
        for (int o = 16; o > 0; o >>= 1) s += __shfl_xor_sync(0xffffffffu, s, o);
        __shared__ double sd[8];
        if (lane == 0) sd[warp] = s;
        __syncthreads();
        if (tid == 0) {
            double tot = 0.0;
            for (int w = 0; w < 8; ++w) tot += sd[w];
            out[0] = (float)tot;
            g_cnt = 0;                       // reset for next graph replay
        }
    }
}

// ---------------------------------------------------------------------------
extern "C" void kernel_launch(void* const* d_in, const int* in_sizes, int n_in,
                              void* d_out, int out_size) {
    const float* input  = (const float*)d_in[0];
    const float* target = (const float*)d_in[1];
    const float* seq    = (const float*)d_in[2];
    const float* fg     = (const float*)d_in[3];

    k_fgsum<<<NFGB + NM, 256>>>((const float4*)fg,
                                (const float4*)input, (const float4*)target);
    k_scan<<<NSCB, 256>>>(seq, (float*)d_out);
}